// round 17
// baseline (speedup 1.0000x reference)
#include <cuda_runtime.h>
#include <cuda_fp16.h>

#define NB    128
#define DR    144            // fine deposit grid rows (x), incl. apron
#define SP2   73             // deposit row stride in half2 words (odd -> bank spread)
#define SH    (SP2*2)        // deposit row stride in halves = 146
#define TW    65             // T row stride in words (65 % 32 == 1 -> conflict-free)
#define OFFS  7              // bin index m -> deposit index m + OFFS
#define NTAP  9              // conv radius 4, Gaussian var = 3/4
#define NBLK  296            // 2 CTAs/SM
#define NTHR  768

__device__ float g_hist[NB * NB];     // accumulated; zeroed at load, re-zeroed by tail
__device__ float g_partial[NBLK];     // per-CTA sums (plain stores)

// Gaussian taps, variance 3/4: w[k] = exp(-(k-4)^2 * 2/3)
__constant__ float W[NTAP] = {
    2.33093e-5f, 2.47875e-3f, 6.94835e-2f, 5.13417e-1f,
    1.0f,
    5.13417e-1f, 6.94835e-2f, 2.47875e-3f, 2.33093e-5f
};

__global__ void __launch_bounds__(NTHR, 2)
accum_kernel(const float* __restrict__ x,
             const float* __restrict__ ex,
             const float* __restrict__ ey,
             int n) {
    extern __shared__ float S[];
    __half2* Dh = (__half2*)S;                    // DR*SP2 words: f16 deposit grid
    const __half* Ds = (const __half*)S;          // scalar half view of D
    __half* Th = (__half*)(S + DR * SP2);         // DR*TW words: f16 intermediate
    __shared__ float red[NTHR / 32];
    const int t = threadIdx.x;

    for (int k = t; k < DR * SP2 + DR * TW; k += NTHR)
        ((unsigned*)S)[k] = 0u;                   // zero D (T overwritten later)
    __syncthreads();

    const float bwx = ex[1] - ex[0];
    const float bwy = ey[1] - ey[0];
    const float inv_bwx = 1.0f / bwx;
    const float inv_bwy = 1.0f / bwy;
    const float c0x = 0.5f * (ex[0] + ex[1]);
    const float c0y = 0.5f * (ey[0] + ey[1]);

    // ---- deposit: TSC 3x3 cloud (t-invariant variance 1/4), f16x2 math ----
    for (int p = blockIdx.x * NTHR + t; p < n; p += NBLK * NTHR) {
        float2 pt = __ldg((const float2*)(x + p * 6));   // dims 0,1; 24B row stride
        float ux = (pt.x - c0x) * inv_bwx;   // bin-center units
        float uy = (pt.y - c0y) * inv_bwy;
        float rx = rintf(ux), ry = rintf(uy);
        int mx = (int)rx, my = (int)ry;
        if (((unsigned)(mx + 6) > 139u) | ((unsigned)(my + 6) > 139u)) continue;
        float tx = ux - rx, ty = uy - ry;    // in [-0.5, 0.5]
        float am = 0.5f - tx, ap = 0.5f + tx;
        float wx0 = 0.5f * am * am, wx2 = 0.5f * ap * ap, wx1 = 0.75f - tx * tx;
        float bm = 0.5f - ty, bp = 0.5f + ty;
        float wy0 = 0.5f * bm * bm, wy2 = 0.5f * bp * bp, wy1 = 0.75f - ty * ty;
        int q = my + OFFS - 1;                       // first y cell (half index)
        int e = q & 1;
        float a0 = e ? 0.0f : wy0;
        float a1 = e ? wy0  : wy1;
        float b0 = e ? wy1  : wy2;
        float b1 = e ? wy2  : 0.0f;
        __half2 hA = __floats2half2_rn(a0, a1);
        __half2 hB = __floats2half2_rn(b0, b1);
        __half2 h0 = __float2half2_rn(wx0);
        __half2 h1 = __float2half2_rn(wx1);
        __half2 h2 = __float2half2_rn(wx2);
        int base = (mx + OFFS - 1) * SP2 + (q >> 1);
        atomicAdd(&Dh[base],           __hmul2(h0, hA));
        atomicAdd(&Dh[base + 1],       __hmul2(h0, hB));
        atomicAdd(&Dh[base + SP2],     __hmul2(h1, hA));
        atomicAdd(&Dh[base + SP2 + 1], __hmul2(h1, hB));
        atomicAdd(&Dh[base + 2*SP2],   __hmul2(h2, hA));
        atomicAdd(&Dh[base + 2*SP2+1], __hmul2(h2, hB));
    }
    __syncthreads();

    // ---- conv1 (y): T[row][j] = sum_d W[d]*D[row][j+d+3], f16 out, 576 thr ----
    if (t < 576) {
        int row = t % DR;
        int j0 = (t / DR) * 32;                      // 4 groups x 32 j
        const __half* Dr = &Ds[row * SH];
        __half2* Tr = (__half2*)&Th[row * 2 * TW];   // word base of this T row
        float buf[NTAP];
        #pragma unroll
        for (int d = 0; d < NTAP - 1; ++d) buf[d] = __half2float(Dr[j0 + 3 + d]);
        #pragma unroll
        for (int k = 0; k < 32; k += 2) {
            buf[(k + NTAP - 1) % NTAP] = __half2float(Dr[j0 + 11 + k]);
            float s0 = 0.0f;
            #pragma unroll
            for (int d = 0; d < NTAP; ++d) s0 = fmaf(W[d], buf[(k + d) % NTAP], s0);
            buf[(k + NTAP) % NTAP] = __half2float(Dr[j0 + 12 + k]);
            float s1 = 0.0f;
            #pragma unroll
            for (int d = 0; d < NTAP; ++d) s1 = fmaf(W[d], buf[(k + 1 + d) % NTAP], s1);
            Tr[(j0 + k) >> 1] = __floats2half2_rn(s0, s1);
        }
    }
    __syncthreads();

    // ---- conv2 (x) + flush + partial sum: 256 threads, half2 j-pairs ----
    float ts = 0.0f;
    if (t < 256) {
        const int jp = t & 63;                       // j-pair 0..63 -> j = 2jp, 2jp+1
        const int i0 = (t >> 6) * 32;                // 4 groups x 32 rows
        const __half2* Tc = (const __half2*)Th;
        float2 buf[NTAP];
        #pragma unroll
        for (int d = 0; d < NTAP - 1; ++d)
            buf[d] = __half22float2(Tc[(i0 + 3 + d) * TW + jp]);
        #pragma unroll
        for (int k = 0; k < 32; ++k) {
            buf[(k + NTAP - 1) % NTAP] = __half22float2(Tc[(i0 + 11 + k) * TW + jp]);
            float sx = 0.0f, sy = 0.0f;
            #pragma unroll
            for (int d = 0; d < NTAP; ++d) {
                float2 b = buf[(k + d) % NTAP];
                sx = fmaf(W[d], b.x, sx);
                sy = fmaf(W[d], b.y, sy);
            }
            ts += sx + sy;
            int o = (i0 + k) * NB + 2 * jp;
            if (sx != 0.0f) atomicAdd(&g_hist[o], sx);
            if (sy != 0.0f) atomicAdd(&g_hist[o + 1], sy);
        }
    }
    // block-reduce ts -> g_partial[blockIdx.x]
    #pragma unroll
    for (int o = 16; o > 0; o >>= 1) ts += __shfl_down_sync(0xffffffffu, ts, o);
    if ((t & 31) == 0) red[t >> 5] = ts;
    __syncthreads();
    if (t < 32) {
        float v = (t < NTHR / 32) ? red[t] : 0.0f;
        #pragma unroll
        for (int o = 16; o > 0; o >>= 1) v += __shfl_down_sync(0xffffffffu, v, o);
        if (t == 0) g_partial[blockIdx.x] = v;
    }
}

// Flat tail: 32 CTAs x 512; each redundantly reduces the 296 partials, then
// scales/writes/rezeros its own 512-element slice.
__global__ void tail_kernel(float* __restrict__ out,
                            const float* __restrict__ ex,
                            const float* __restrict__ ey) {
    __shared__ float red[16];
    __shared__ float s_scale;
    const int t = threadIdx.x;

    float v = (t < NBLK) ? g_partial[t] : 0.0f;
    #pragma unroll
    for (int o = 16; o > 0; o >>= 1) v += __shfl_down_sync(0xffffffffu, v, o);
    if ((t & 31) == 0) red[t >> 5] = v;
    __syncthreads();
    if (t < 32) {
        float w = (t < 16) ? red[t] : 0.0f;
        #pragma unroll
        for (int o = 8; o > 0; o >>= 1) w += __shfl_down_sync(0xffffffffu, w, o);
        if (t == 0) {
            float bwx = ex[1] - ex[0], bwy = ey[1] - ey[0];
            s_scale = 1.0f / (w * bwx * bwy);
        }
    }
    __syncthreads();
    int idx = blockIdx.x * 512 + t;
    out[idx] = g_hist[idx] * s_scale;
    g_hist[idx] = 0.0f;       // reset for next graph replay
}

extern "C" void kernel_launch(void* const* d_in, const int* in_sizes, int n_in,
                              void* d_out, int out_size) {
    const float* x  = (const float*)d_in[0];
    const float* ex = (const float*)d_in[1];
    const float* ey = (const float*)d_in[2];
    int n = in_sizes[0] / 6;

    const int SMEM = (DR * SP2 + DR * TW) * (int)sizeof(float);   // 79488 B -> 2 CTAs/SM
    cudaFuncSetAttribute(accum_kernel, cudaFuncAttributeMaxDynamicSharedMemorySize, SMEM);

    accum_kernel<<<NBLK, NTHR, SMEM>>>(x, ex, ey, n);
    tail_kernel<<<(NB * NB) / 512, 512>>>((float*)d_out, ex, ey);
}